// round 2
// baseline (speedup 1.0000x reference)
#include <cuda_runtime.h>
#include <cuda_bf16.h>
#include <math.h>

#define N_NODES 100000
#define N_EDGES 1600000
#define F1 64
#define F2 40
#define KDIM 500

// ---------------- scratch (static device globals; no allocation) ----------------
__device__ int   g_counts[N_NODES];
__device__ int   g_rowptr[N_NODES + 1];
__device__ int   g_pos[N_NODES];
__device__ int   g_col[N_EDGES];
__device__ int   g_bsum[512];
__device__ float g_dinv[N_NODES];
__device__ float g_h1[(size_t)N_NODES * F1];   // (x@W1)*dinv  (scaled rows)
__device__ float g_o1[(size_t)N_NODES * F1];   // relu(dinv*agg + b1)
__device__ float g_h2[(size_t)N_NODES * F2];   // (o1@W2)*dinv

// ---------------- small utils ----------------
__device__ __forceinline__ int warp_incl_scan(int v, unsigned lane) {
#pragma unroll
    for (int o = 1; o < 32; o <<= 1) {
        int n = __shfl_up_sync(0xffffffffu, v, o);
        if (lane >= o) v += n;
    }
    return v;
}

// ---------------- degree / CSR build ----------------
__global__ void zero_counts_kernel() {
    int i = blockIdx.x * 256 + threadIdx.x;
    if (i < N_NODES) g_counts[i] = 0;
}

__global__ void count_kernel(const int* __restrict__ ei) {
    int e = blockIdx.x * 256 + threadIdx.x;
    if (e < N_EDGES) {
        int d = ei[N_EDGES + e];   // dst (int32)
        atomicAdd(&g_counts[d], 1);
    }
}

__global__ void dinv_kernel() {
    int i = blockIdx.x * 256 + threadIdx.x;
    if (i < N_NODES) {
        // deg includes the self-loop -> counts + 1 >= 1
        g_dinv[i] = rsqrtf((float)(g_counts[i] + 1));
    }
}

__global__ void scan1_kernel() {
    __shared__ int wsum[8];
    int i = blockIdx.x * 256 + threadIdx.x;
    unsigned lane = threadIdx.x & 31;
    int wid = threadIdx.x >> 5;
    int v = (i < N_NODES) ? g_counts[i] : 0;
    int inc = warp_incl_scan(v, lane);
    if (lane == 31) wsum[wid] = inc;
    __syncthreads();
    if (wid == 0) {
        int s = (lane < 8) ? wsum[lane] : 0;
        s = warp_incl_scan(s, lane);
        if (lane < 8) wsum[lane] = s;
    }
    __syncthreads();
    int off = wid ? wsum[wid - 1] : 0;
    if (i < N_NODES) g_rowptr[i] = off + inc - v;       // block-local exclusive
    if (threadIdx.x == 255) g_bsum[blockIdx.x] = off + inc;  // block total
}

__global__ void scan2_kernel(int nblocks) {
    __shared__ int wsum[16];
    int t = threadIdx.x;
    unsigned lane = t & 31;
    int wid = t >> 5;
    int v = (t < nblocks) ? g_bsum[t] : 0;
    int inc = warp_incl_scan(v, lane);
    if (lane == 31) wsum[wid] = inc;
    __syncthreads();
    if (wid == 0) {
        int s = (lane < 16) ? wsum[lane] : 0;
        s = warp_incl_scan(s, lane);
        if (lane < 16) wsum[lane] = s;
    }
    __syncthreads();
    int off = wid ? wsum[wid - 1] : 0;
    if (t < nblocks) g_bsum[t] = off + inc - v;          // exclusive
}

__global__ void scan3_kernel() {
    int i = blockIdx.x * 256 + threadIdx.x;
    if (i < N_NODES) {
        int r = g_rowptr[i] + g_bsum[blockIdx.x];
        g_rowptr[i] = r;
        g_pos[i] = r;
    }
    if (i == 0) g_rowptr[N_NODES] = N_EDGES;
}

__global__ void scatter_kernel(const int* __restrict__ ei) {
    int e = blockIdx.x * 256 + threadIdx.x;
    if (e < N_EDGES) {
        int s = ei[e];
        int d = ei[N_EDGES + e];
        int p = atomicAdd(&g_pos[d], 1);
        g_col[p] = s;
    }
}

// ---------------- GEMM1: h1 = (x @ W1) * dinv[row]  [100000x500 @ 500x64] ----------------
// block: 256 threads = 64 cols x 4 row-quads; 32 rows per block, 8 rows per thread.
__global__ void gemm1_kernel(const float* __restrict__ x, const float* __restrict__ W) {
    __shared__ float xs[32 * 64];
    int row0 = blockIdx.x * 32;
    int c = threadIdx.x & 63;
    int rq = threadIdx.x >> 6;     // 0..3

    float acc[8];
#pragma unroll
    for (int p = 0; p < 8; p++) acc[p] = 0.f;

    for (int k0 = 0; k0 < 512; k0 += 64) {
        __syncthreads();
#pragma unroll
        for (int i = 0; i < 8; i++) {
            int idx = threadIdx.x + i * 256;   // 0..2047 over (r, kk)
            int r = idx >> 6, kk = idx & 63;
            int k = k0 + kk;
            xs[r * 64 + kk] = (k < KDIM) ? x[(size_t)(row0 + r) * KDIM + k] : 0.f;
        }
        __syncthreads();
#pragma unroll 16
        for (int kk = 0; kk < 64; kk++) {
            int k = k0 + kk;
            float w = (k < KDIM) ? W[k * F1 + c] : 0.f;
#pragma unroll
            for (int p = 0; p < 8; p++)
                acc[p] = fmaf(xs[(rq * 8 + p) * 64 + kk], w, acc[p]);
        }
    }
#pragma unroll
    for (int p = 0; p < 8; p++) {
        int r = row0 + rq * 8 + p;
        g_h1[(size_t)r * F1 + c] = acc[p] * g_dinv[r];
    }
}

// ---------------- agg1: o1 = relu(dinv_i * (h1_i + sum_{s in in(i)} h1_s) + b1) ----------------
// one warp per node, lane covers features l and l+32.
__global__ void agg1_kernel(const float* __restrict__ b1) {
    int warp = (blockIdx.x * blockDim.x + threadIdx.x) >> 5;
    int lane = threadIdx.x & 31;
    if (warp >= N_NODES) return;
    int i = warp;

    const float* __restrict__ h = g_h1;
    float a0 = h[(size_t)i * F1 + lane];
    float a1 = h[(size_t)i * F1 + 32 + lane];

    int e = g_rowptr[i], e1 = g_rowptr[i + 1];
    for (; e + 3 < e1; e += 4) {
        int s0 = g_col[e], s1 = g_col[e + 1], s2 = g_col[e + 2], s3 = g_col[e + 3];
        float v0 = h[(size_t)s0 * F1 + lane],     u0 = h[(size_t)s0 * F1 + 32 + lane];
        float v1 = h[(size_t)s1 * F1 + lane],     u1 = h[(size_t)s1 * F1 + 32 + lane];
        float v2 = h[(size_t)s2 * F1 + lane],     u2 = h[(size_t)s2 * F1 + 32 + lane];
        float v3 = h[(size_t)s3 * F1 + lane],     u3 = h[(size_t)s3 * F1 + 32 + lane];
        a0 += (v0 + v1) + (v2 + v3);
        a1 += (u0 + u1) + (u2 + u3);
    }
    for (; e < e1; e++) {
        int s = g_col[e];
        a0 += h[(size_t)s * F1 + lane];
        a1 += h[(size_t)s * F1 + 32 + lane];
    }
    float di = g_dinv[i];
    g_o1[(size_t)i * F1 + lane]      = fmaxf(fmaf(di, a0, b1[lane]), 0.f);
    g_o1[(size_t)i * F1 + 32 + lane] = fmaxf(fmaf(di, a1, b1[32 + lane]), 0.f);
}

// ---------------- GEMM2: h2 = (o1 @ W2) * dinv[row]  [100000x64 @ 64x40] ----------------
__global__ void gemm2_kernel(const float* __restrict__ W) {
    __shared__ float xs[32 * 64];
    int row0 = blockIdx.x * 32;
    int c = threadIdx.x & 63;
    int rq = threadIdx.x >> 6;

#pragma unroll
    for (int i = 0; i < 8; i++) {
        int idx = threadIdx.x + i * 256;
        int r = idx >> 6, kk = idx & 63;
        xs[r * 64 + kk] = g_o1[(size_t)(row0 + r) * F1 + kk];
    }
    __syncthreads();
    if (c < F2) {
        float acc[8];
#pragma unroll
        for (int p = 0; p < 8; p++) acc[p] = 0.f;
#pragma unroll 16
        for (int kk = 0; kk < 64; kk++) {
            float w = W[kk * F2 + c];
#pragma unroll
            for (int p = 0; p < 8; p++)
                acc[p] = fmaf(xs[(rq * 8 + p) * 64 + kk], w, acc[p]);
        }
#pragma unroll
        for (int p = 0; p < 8; p++) {
            int r = row0 + rq * 8 + p;
            g_h2[(size_t)r * F2 + c] = acc[p] * g_dinv[r];
        }
    }
}

// ---------------- agg2 + bias + log_softmax -> d_out ----------------
// one warp per node; lane holds feature l, and feature l+32 for l<8.
__global__ void agg2_kernel(const float* __restrict__ b2, float* __restrict__ out) {
    int warp = (blockIdx.x * blockDim.x + threadIdx.x) >> 5;
    int lane = threadIdx.x & 31;
    if (warp >= N_NODES) return;
    int i = warp;
    bool hi = (lane < 8);

    const float* __restrict__ h = g_h2;
    float a0 = h[(size_t)i * F2 + lane];
    float a1 = hi ? h[(size_t)i * F2 + 32 + lane] : 0.f;

    int e = g_rowptr[i], e1 = g_rowptr[i + 1];
    for (; e + 3 < e1; e += 4) {
        int s0 = g_col[e], s1 = g_col[e + 1], s2 = g_col[e + 2], s3 = g_col[e + 3];
        float v0 = h[(size_t)s0 * F2 + lane];
        float v1 = h[(size_t)s1 * F2 + lane];
        float v2 = h[(size_t)s2 * F2 + lane];
        float v3 = h[(size_t)s3 * F2 + lane];
        a0 += (v0 + v1) + (v2 + v3);
        if (hi) {
            float u0 = h[(size_t)s0 * F2 + 32 + lane];
            float u1 = h[(size_t)s1 * F2 + 32 + lane];
            float u2 = h[(size_t)s2 * F2 + 32 + lane];
            float u3 = h[(size_t)s3 * F2 + 32 + lane];
            a1 += (u0 + u1) + (u2 + u3);
        }
    }
    for (; e < e1; e++) {
        int s = g_col[e];
        a0 += h[(size_t)s * F2 + lane];
        if (hi) a1 += h[(size_t)s * F2 + 32 + lane];
    }

    float di = g_dinv[i];
    float z0 = fmaf(di, a0, b2[lane]);
    float z1 = hi ? fmaf(di, a1, b2[32 + lane]) : -1e30f;

    // log_softmax over 40 logits held across the warp
    float m = fmaxf(z0, z1);
#pragma unroll
    for (int o = 16; o > 0; o >>= 1) m = fmaxf(m, __shfl_xor_sync(0xffffffffu, m, o));
    float s = expf(z0 - m) + (hi ? expf(z1 - m) : 0.f);
#pragma unroll
    for (int o = 16; o > 0; o >>= 1) s += __shfl_xor_sync(0xffffffffu, s, o);
    float lse = m + logf(s);

    out[(size_t)i * F2 + lane] = z0 - lse;
    if (hi) out[(size_t)i * F2 + 32 + lane] = z1 - lse;
}

// ---------------- launch ----------------
extern "C" void kernel_launch(void* const* d_in, const int* in_sizes, int n_in,
                              void* d_out, int out_size) {
    const float* x  = (const float*)d_in[0];
    const int*   ei = (const int*)d_in[1];     // int32! (JAX x64 disabled downgrades int64)
    const float* W1 = (const float*)d_in[2];
    const float* b1 = (const float*)d_in[3];
    const float* W2 = (const float*)d_in[4];
    const float* b2 = (const float*)d_in[5];
    float* out = (float*)d_out;

    const int nb_nodes = (N_NODES + 255) / 256;   // 391
    const int nb_edges = (N_EDGES + 255) / 256;   // 6250

    // degree + dinv
    zero_counts_kernel<<<nb_nodes, 256>>>();
    count_kernel<<<nb_edges, 256>>>(ei);
    dinv_kernel<<<nb_nodes, 256>>>();

    // CSR build (rowptr scan + scatter)
    scan1_kernel<<<nb_nodes, 256>>>();
    scan2_kernel<<<1, 512>>>(nb_nodes);
    scan3_kernel<<<nb_nodes, 256>>>();
    scatter_kernel<<<nb_edges, 256>>>(ei);

    // layer 1
    gemm1_kernel<<<N_NODES / 32, 256>>>(x, W1);
    agg1_kernel<<<(N_NODES * 32 + 255) / 256, 256>>>(b1);

    // layer 2
    gemm2_kernel<<<N_NODES / 32, 256>>>(W2);
    agg2_kernel<<<(N_NODES * 32 + 255) / 256, 256>>>(b2, out);
}

// round 4
// speedup vs baseline: 1.9812x; 1.9812x over previous
#include <cuda_runtime.h>
#include <cuda_bf16.h>
#include <math.h>
#include <stdint.h>

#define N_NODES 100000
#define N_EDGES 1600000
#define F1 64
#define F2 40
#define KDIM 500
#define KPAD 512

// ---------------- scratch (static device globals; no allocation) ----------------
__device__ int   g_counts[N_NODES];
__device__ int   g_rowptr[N_NODES + 1];
__device__ int   g_pos[N_NODES];
__device__ int   g_col[N_EDGES];
__device__ int   g_bsum[512];
__device__ float g_dinv[N_NODES];
__device__ float g_h1[(size_t)N_NODES * F1];   // (x@W1)*dinv  (scaled rows)
__device__ float g_o1[(size_t)N_NODES * F1];   // relu(dinv*agg + b1)
__device__ float g_h2[(size_t)N_NODES * F2];   // (o1@W2)*dinv
__device__ __nv_bfloat16 g_wh[64 * KPAD];      // W1 split-hi, [n][k] K-major, padded
__device__ __nv_bfloat16 g_wl[64 * KPAD];      // W1 split-lo

// ---------------- PTX helpers (plain sm_103-safe: ldmatrix + mma.sync only) ----------------
__device__ __forceinline__ uint32_t smem_u32(const void* p) {
    uint32_t a;
    asm("{ .reg .u64 t; cvta.to.shared.u64 t, %1; cvt.u32.u64 %0, t; }" : "=r"(a) : "l"(p));
    return a;
}
__device__ __forceinline__ void ldm_x4(uint32_t* r, uint32_t addr) {
    asm volatile("ldmatrix.sync.aligned.m8n8.x4.shared.b16 {%0,%1,%2,%3}, [%4];"
                 : "=r"(r[0]), "=r"(r[1]), "=r"(r[2]), "=r"(r[3]) : "r"(addr));
}
__device__ __forceinline__ void mma_bf16(float* d, const uint32_t* a, uint32_t b0, uint32_t b1) {
    asm volatile("mma.sync.aligned.m16n8k16.row.col.f32.bf16.bf16.f32 "
                 "{%0,%1,%2,%3}, {%4,%5,%6,%7}, {%8,%9}, {%0,%1,%2,%3};"
                 : "+f"(d[0]), "+f"(d[1]), "+f"(d[2]), "+f"(d[3])
                 : "r"(a[0]), "r"(a[1]), "r"(a[2]), "r"(a[3]), "r"(b0), "r"(b1));
}

// ---------------- small utils ----------------
__device__ __forceinline__ int warp_incl_scan(int v, unsigned lane) {
#pragma unroll
    for (int o = 1; o < 32; o <<= 1) {
        int n = __shfl_up_sync(0xffffffffu, v, o);
        if (lane >= o) v += n;
    }
    return v;
}

// ---------------- degree / CSR build ----------------
__global__ void zero_counts_kernel() {
    int i = blockIdx.x * 256 + threadIdx.x;
    if (i < N_NODES) g_counts[i] = 0;
}

__global__ void count_kernel(const int* __restrict__ ei) {
    int e = blockIdx.x * 256 + threadIdx.x;
    if (e < N_EDGES) atomicAdd(&g_counts[ei[N_EDGES + e]], 1);
}

__global__ void dinv_kernel() {
    int i = blockIdx.x * 256 + threadIdx.x;
    if (i < N_NODES) g_dinv[i] = rsqrtf((float)(g_counts[i] + 1));
}

__global__ void scan1_kernel() {
    __shared__ int wsum[8];
    int i = blockIdx.x * 256 + threadIdx.x;
    unsigned lane = threadIdx.x & 31;
    int wid = threadIdx.x >> 5;
    int v = (i < N_NODES) ? g_counts[i] : 0;
    int inc = warp_incl_scan(v, lane);
    if (lane == 31) wsum[wid] = inc;
    __syncthreads();
    if (wid == 0) {
        int s = (lane < 8) ? wsum[lane] : 0;
        s = warp_incl_scan(s, lane);
        if (lane < 8) wsum[lane] = s;
    }
    __syncthreads();
    int off = wid ? wsum[wid - 1] : 0;
    if (i < N_NODES) g_rowptr[i] = off + inc - v;
    if (threadIdx.x == 255) g_bsum[blockIdx.x] = off + inc;
}

__global__ void scan2_kernel(int nblocks) {
    __shared__ int wsum[16];
    int t = threadIdx.x;
    unsigned lane = t & 31;
    int wid = t >> 5;
    int v = (t < nblocks) ? g_bsum[t] : 0;
    int inc = warp_incl_scan(v, lane);
    if (lane == 31) wsum[wid] = inc;
    __syncthreads();
    if (wid == 0) {
        int s = (lane < 16) ? wsum[lane] : 0;
        s = warp_incl_scan(s, lane);
        if (lane < 16) wsum[lane] = s;
    }
    __syncthreads();
    int off = wid ? wsum[wid - 1] : 0;
    if (t < nblocks) g_bsum[t] = off + inc - v;
}

__global__ void scan3_kernel() {
    int i = blockIdx.x * 256 + threadIdx.x;
    if (i < N_NODES) {
        int r = g_rowptr[i] + g_bsum[blockIdx.x];
        g_rowptr[i] = r;
        g_pos[i] = r;
    }
    if (i == 0) g_rowptr[N_NODES] = N_EDGES;
}

__global__ void scatter_kernel(const int* __restrict__ ei) {
    int e = blockIdx.x * 256 + threadIdx.x;
    if (e < N_EDGES) {
        int s = ei[e];
        int d = ei[N_EDGES + e];
        int p = atomicAdd(&g_pos[d], 1);
        g_col[p] = s;
    }
}

// ---------------- W1 split into bf16 hi/lo, K-major [n][k], k padded to 512 ----------------
__global__ void wsplit_kernel(const float* __restrict__ W) {
    int idx = blockIdx.x * 512 + threadIdx.x;   // 64*512 entries
    int n = idx >> 9, k = idx & 511;
    float v = (k < KDIM) ? W[k * F1 + n] : 0.f;
    __nv_bfloat16 h = __float2bfloat16_rn(v);
    __nv_bfloat16 l = __float2bfloat16_rn(v - __bfloat162float(h));
    g_wh[idx] = h;
    g_wl[idx] = l;
}

// ---------------- GEMM1 via mma.sync bf16 split: h1 = (x @ W1) * dinv[row] ----------------
// Block 256 thr = 8 warps. Tile M=128 (16 rows/warp), N=64. K staged 64 fp32 at a time.
// smem: AH[16K] AL[16K] BH[8K] BL[8K]; rows are 64 bf16 = 128B; 16B-unit XOR swizzle.
__global__ void __launch_bounds__(256) gemm1_mma_kernel(const float* __restrict__ x) {
    extern __shared__ char smem[];
    const int OFF_AH = 0, OFF_AL = 16384, OFF_BH = 32768, OFF_BL = 40960;
    uint32_t sb = smem_u32(smem);
    int tid = threadIdx.x;
    int warp = tid >> 5, lane = tid & 31;
    int row0 = blockIdx.x * 128;
    int wr0 = warp * 16;

    float d[8][4];
#pragma unroll
    for (int nt = 0; nt < 8; nt++)
#pragma unroll
        for (int q = 0; q < 4; q++) d[nt][q] = 0.f;

    for (int c = 0; c < 8; c++) {
        __syncthreads();   // previous compute done before restaging
        int k0 = c * 64;

        // ---- stage A: 128 rows x 32 bf16-pairs; split fp32 -> hi/lo bf16 ----
#pragma unroll
        for (int i = 0; i < 16; i++) {
            int p = tid + i * 256;
            int r = p >> 5, pk = p & 31;
            int k = k0 + pk * 2;
            int row = row0 + r;
            float v0 = 0.f, v1 = 0.f;
            if (row < N_NODES && k < KDIM) {
                float2 xv = *reinterpret_cast<const float2*>(&x[(size_t)row * KDIM + k]);
                v0 = xv.x; v1 = xv.y;
            }
            __nv_bfloat162 hp = __floats2bfloat162_rn(v0, v1);
            __nv_bfloat162 lp = __floats2bfloat162_rn(v0 - __bfloat162float(hp.x),
                                                      v1 - __bfloat162float(hp.y));
            unsigned off = (unsigned)(r * 128 + ((((pk >> 2) ^ (r & 7)) << 4)) + (pk & 3) * 4);
            *reinterpret_cast<unsigned*>(smem + OFF_AH + off) = *reinterpret_cast<unsigned*>(&hp);
            *reinterpret_cast<unsigned*>(smem + OFF_AL + off) = *reinterpret_cast<unsigned*>(&lp);
        }
        // ---- stage B: 64 n-rows x 32 bf16-pairs (pre-split, K-major) ----
#pragma unroll
        for (int i = 0; i < 8; i++) {
            int p = tid + i * 256;
            int n = p >> 5, pk = p & 31;
            unsigned hu = *reinterpret_cast<const unsigned*>(&g_wh[n * KPAD + k0 + pk * 2]);
            unsigned lu = *reinterpret_cast<const unsigned*>(&g_wl[n * KPAD + k0 + pk * 2]);
            unsigned off = (unsigned)(n * 128 + ((((pk >> 2) ^ (n & 7)) << 4)) + (pk & 3) * 4);
            *reinterpret_cast<unsigned*>(smem + OFF_BH + off) = hu;
            *reinterpret_cast<unsigned*>(smem + OFF_BL + off) = lu;
        }
        __syncthreads();

        // ---- compute: 4 k16 sub-chunks ----
#pragma unroll
        for (int ks = 0; ks < 4; ks++) {
            int m = lane >> 3, li = lane & 7;
            // A fragments (16x16): matrices (r0-7,k0-7)(r8-15,k0-7)(r0-7,k8-15)(r8-15,k8-15)
            int arow = wr0 + li + (m & 1) * 8;
            int akb  = ks * 16 + (m >> 1) * 8;
            uint32_t aoff = (unsigned)(arow * 128 + (((akb >> 3) ^ (arow & 7)) << 4));
            uint32_t ah[4], al[4];
            ldm_x4(ah, sb + OFF_AH + aoff);
            ldm_x4(al, sb + OFF_AL + aoff);
            // B fragments: per x4, two n-tiles: (n0-7,k0-7)(n0-7,k8-15)(n8-15,k0-7)(n8-15,k8-15)
            uint32_t bh[16], bl[16];
#pragma unroll
            for (int j = 0; j < 4; j++) {
                int nrow = j * 16 + (m >> 1) * 8 + li;
                int bkb  = ks * 16 + (m & 1) * 8;
                uint32_t boff = (unsigned)(nrow * 128 + (((bkb >> 3) ^ (nrow & 7)) << 4));
                ldm_x4(&bh[j * 4], sb + OFF_BH + boff);
                ldm_x4(&bl[j * 4], sb + OFF_BL + boff);
            }
#pragma unroll
            for (int nt = 0; nt < 8; nt++) {
                int bi = (nt >> 1) * 4 + (nt & 1) * 2;
                mma_bf16(d[nt], ah, bh[bi], bh[bi + 1]);   // xh*wh
                mma_bf16(d[nt], ah, bl[bi], bl[bi + 1]);   // xh*wl
                mma_bf16(d[nt], al, bh[bi], bh[bi + 1]);   // xl*wh
            }
        }
    }

    // ---- epilogue: scale by dinv, store ----
    int g = lane >> 2, tq = lane & 3;
    int r_lo = row0 + wr0 + g;
    int r_hi = r_lo + 8;
    float di_lo = (r_lo < N_NODES) ? g_dinv[r_lo] : 0.f;
    float di_hi = (r_hi < N_NODES) ? g_dinv[r_hi] : 0.f;
#pragma unroll
    for (int nt = 0; nt < 8; nt++) {
        int col = nt * 8 + tq * 2;
        if (r_lo < N_NODES) {
            float2 v = make_float2(d[nt][0] * di_lo, d[nt][1] * di_lo);
            *reinterpret_cast<float2*>(&g_h1[(size_t)r_lo * F1 + col]) = v;
        }
        if (r_hi < N_NODES) {
            float2 v = make_float2(d[nt][2] * di_hi, d[nt][3] * di_hi);
            *reinterpret_cast<float2*>(&g_h1[(size_t)r_hi * F1 + col]) = v;
        }
    }
}

// ---------------- agg1: o1 = relu(dinv_i * (h1_i + sum_{s in in(i)} h1_s) + b1) ----------------
__global__ void agg1_kernel(const float* __restrict__ b1) {
    int warp = (blockIdx.x * blockDim.x + threadIdx.x) >> 5;
    int lane = threadIdx.x & 31;
    if (warp >= N_NODES) return;
    int i = warp;

    const float* __restrict__ h = g_h1;
    float a0 = h[(size_t)i * F1 + lane];
    float a1 = h[(size_t)i * F1 + 32 + lane];

    int e = g_rowptr[i], e1 = g_rowptr[i + 1];
    for (; e + 3 < e1; e += 4) {
        int s0 = g_col[e], s1 = g_col[e + 1], s2 = g_col[e + 2], s3 = g_col[e + 3];
        float v0 = h[(size_t)s0 * F1 + lane],     u0 = h[(size_t)s0 * F1 + 32 + lane];
        float v1 = h[(size_t)s1 * F1 + lane],     u1 = h[(size_t)s1 * F1 + 32 + lane];
        float v2 = h[(size_t)s2 * F1 + lane],     u2 = h[(size_t)s2 * F1 + 32 + lane];
        float v3 = h[(size_t)s3 * F1 + lane],     u3 = h[(size_t)s3 * F1 + 32 + lane];
        a0 += (v0 + v1) + (v2 + v3);
        a1 += (u0 + u1) + (u2 + u3);
    }
    for (; e < e1; e++) {
        int s = g_col[e];
        a0 += h[(size_t)s * F1 + lane];
        a1 += h[(size_t)s * F1 + 32 + lane];
    }
    float di = g_dinv[i];
    g_o1[(size_t)i * F1 + lane]      = fmaxf(fmaf(di, a0, b1[lane]), 0.f);
    g_o1[(size_t)i * F1 + 32 + lane] = fmaxf(fmaf(di, a1, b1[32 + lane]), 0.f);
}

// ---------------- GEMM2: h2 = (o1 @ W2) * dinv[row]  [100000x64 @ 64x40] ----------------
__global__ void gemm2_kernel(const float* __restrict__ W) {
    __shared__ float xs[32 * 64];
    int row0 = blockIdx.x * 32;
    int c = threadIdx.x & 63;
    int rq = threadIdx.x >> 6;

#pragma unroll
    for (int i = 0; i < 8; i++) {
        int idx = threadIdx.x + i * 256;
        int r = idx >> 6, kk = idx & 63;
        xs[r * 64 + kk] = g_o1[(size_t)(row0 + r) * F1 + kk];
    }
    __syncthreads();
    if (c < F2) {
        float acc[8];
#pragma unroll
        for (int p = 0; p < 8; p++) acc[p] = 0.f;
#pragma unroll 16
        for (int kk = 0; kk < 64; kk++) {
            float w = W[kk * F2 + c];
#pragma unroll
            for (int p = 0; p < 8; p++)
                acc[p] = fmaf(xs[(rq * 8 + p) * 64 + kk], w, acc[p]);
        }
#pragma unroll
        for (int p = 0; p < 8; p++) {
            int r = row0 + rq * 8 + p;
            g_h2[(size_t)r * F2 + c] = acc[p] * g_dinv[r];
        }
    }
}

// ---------------- agg2 + bias + log_softmax -> d_out ----------------
__global__ void agg2_kernel(const float* __restrict__ b2, float* __restrict__ out) {
    int warp = (blockIdx.x * blockDim.x + threadIdx.x) >> 5;
    int lane = threadIdx.x & 31;
    if (warp >= N_NODES) return;
    int i = warp;
    bool hi = (lane < 8);

    const float* __restrict__ h = g_h2;
    float a0 = h[(size_t)i * F2 + lane];
    float a1 = hi ? h[(size_t)i * F2 + 32 + lane] : 0.f;

    int e = g_rowptr[i], e1 = g_rowptr[i + 1];
    for (; e + 3 < e1; e += 4) {
        int s0 = g_col[e], s1 = g_col[e + 1], s2 = g_col[e + 2], s3 = g_col[e + 3];
        float v0 = h[(size_t)s0 * F2 + lane];
        float v1 = h[(size_t)s1 * F2 + lane];
        float v2 = h[(size_t)s2 * F2 + lane];
        float v3 = h[(size_t)s3 * F2 + lane];
        a0 += (v0 + v1) + (v2 + v3);
        if (hi) {
            float u0 = h[(size_t)s0 * F2 + 32 + lane];
            float u1 = h[(size_t)s1 * F2 + 32 + lane];
            float u2 = h[(size_t)s2 * F2 + 32 + lane];
            float u3 = h[(size_t)s3 * F2 + 32 + lane];
            a1 += (u0 + u1) + (u2 + u3);
        }
    }
    for (; e < e1; e++) {
        int s = g_col[e];
        a0 += h[(size_t)s * F2 + lane];
        if (hi) a1 += h[(size_t)s * F2 + 32 + lane];
    }

    float di = g_dinv[i];
    float z0 = fmaf(di, a0, b2[lane]);
    float z1 = hi ? fmaf(di, a1, b2[32 + lane]) : -1e30f;

    float m = fmaxf(z0, z1);
#pragma unroll
    for (int o = 16; o > 0; o >>= 1) m = fmaxf(m, __shfl_xor_sync(0xffffffffu, m, o));
    float s = expf(z0 - m) + (hi ? expf(z1 - m) : 0.f);
#pragma unroll
    for (int o = 16; o > 0; o >>= 1) s += __shfl_xor_sync(0xffffffffu, s, o);
    float lse = m + logf(s);

    out[(size_t)i * F2 + lane] = z0 - lse;
    if (hi) out[(size_t)i * F2 + 32 + lane] = z1 - lse;
}

// ---------------- launch ----------------
extern "C" void kernel_launch(void* const* d_in, const int* in_sizes, int n_in,
                              void* d_out, int out_size) {
    const float* x  = (const float*)d_in[0];
    const int*   ei = (const int*)d_in[1];     // int32 (JAX x64 disabled)
    const float* W1 = (const float*)d_in[2];
    const float* b1 = (const float*)d_in[3];
    const float* W2 = (const float*)d_in[4];
    const float* b2 = (const float*)d_in[5];
    float* out = (float*)d_out;

    const int nb_nodes = (N_NODES + 255) / 256;   // 391
    const int nb_edges = (N_EDGES + 255) / 256;   // 6250
    const int GEMM1_SMEM = 49152;

    cudaFuncSetAttribute(gemm1_mma_kernel, cudaFuncAttributeMaxDynamicSharedMemorySize, GEMM1_SMEM);

    // W1 split (independent of graph build)
    wsplit_kernel<<<64, 512>>>(W1);

    // degree + dinv
    zero_counts_kernel<<<nb_nodes, 256>>>();
    count_kernel<<<nb_edges, 256>>>(ei);
    dinv_kernel<<<nb_nodes, 256>>>();

    // CSR build
    scan1_kernel<<<nb_nodes, 256>>>();
    scan2_kernel<<<1, 512>>>(nb_nodes);
    scan3_kernel<<<nb_nodes, 256>>>();
    scatter_kernel<<<nb_edges, 256>>>(ei);

    // layer 1 (mma.sync split-bf16 GEMM)
    gemm1_mma_kernel<<<(N_NODES + 127) / 128, 256, GEMM1_SMEM>>>(x);
    agg1_kernel<<<(N_NODES * 32 + 255) / 256, 256>>>(b1);

    // layer 2
    gemm2_kernel<<<N_NODES / 32, 256>>>(W2);
    agg2_kernel<<<(N_NODES * 32 + 255) / 256, 256>>>(b2, out);
}